// round 9
// baseline (speedup 1.0000x reference)
#include <cuda_runtime.h>
#include <cuda_fp16.h>
#include <cstdint>

#define BB 8
#define NQ 32
#define LQ 128
#define NK 16
#define LK 256
#define DD 128
#define KQ 64
#define KK 128
#define NEGV -99999.0f
#define PADD 136

// K2 smem: ctxt double buffer 2x(128 x PADD) + cand 64 x PADD halfs + rowmax[128]
#define ABUF_H   (128 * PADD)                 // halfs per ctxt buffer
#define SM_B_H   (2 * ABUF_H)                 // cand offset (halfs)
#define SM_RM_B  ((2 * ABUF_H + 64 * PADD) * 2)   // rowmax offset (bytes)
#define SMEM_K2  (SM_RM_B + 128 * 4)

__device__ __align__(16) __half g_candSel[BB*NQ*KQ*DD];
__device__ __align__(16) __half g_ctxtSel[BB*NK*KK*DD];
__device__ int   g_candValid[BB*NQ];
__device__ float g_ctxtMask[BB*NK*KK];

__device__ __forceinline__ unsigned int fkey(float f) {
    unsigned int u = __float_as_uint(f);
    return (u & 0x80000000u) ? ~u : (u | 0x80000000u);
}
__device__ __forceinline__ int mask_mode(const unsigned char* m) {
    const unsigned int* w = (const unsigned int*)m;
    #pragma unroll
    for (int i = 0; i < 4; i++) {
        unsigned int v = w[i];
        if (v == 0x3F800000u) return 2;
        if (v > 1u) return 0;
    }
    return 1;
}
__device__ __forceinline__ bool read_mask(const unsigned char* m, int i, int mode) {
    if (mode == 0) return m[i] != 0;
    if (mode == 1) return ((const int*)m)[i] != 0;
    return ((const float*)m)[i] != 0.0f;
}

// ---------------------------------------------------------------------------
// Kernel 1: scores -> bitonic top-k -> gather to fp16 scratch (512 threads)
// ---------------------------------------------------------------------------
__global__ __launch_bounds__(512) void select_gather_kernel(
    const float* __restrict__ cand, const float* __restrict__ ctxt,
    const unsigned char* __restrict__ mcand, const unsigned char* __restrict__ mctxt,
    const float* __restrict__ W, const float* __restrict__ bptr)
{
    __shared__ __align__(16) float Ws[DD];
    __shared__ unsigned long long keys[256];
    __shared__ int s_count;

    int tid = threadIdx.x;
    bool isCand = (blockIdx.x < BB*NQ);
    int row = isCand ? blockIdx.x : (blockIdx.x - BB*NQ);
    int L = isCand ? LQ : LK;
    int k = L >> 1;
    const float* rep = isCand ? (cand + (size_t)row * LQ * DD)
                              : (ctxt + (size_t)row * LK * DD);
    const unsigned char* mbase = isCand ? mcand : mctxt;
    int mmode = mask_mode(mbase);
    int moff  = row * L;

    if (tid < DD) Ws[tid] = W[tid];
    if (tid == 0) s_count = 0;
    __syncthreads();

    float bb = bptr[0];
    int wid = tid >> 5, lane = tid & 31;

    for (int t = wid; t < L; t += 16) {
        float4 v  = ((const float4*)(rep + t * DD))[lane];
        float4 w4 = ((const float4*)Ws)[lane];
        float acc = v.x*w4.x + v.y*w4.y + v.z*w4.z + v.w*w4.w;
        #pragma unroll
        for (int off = 16; off; off >>= 1) acc += __shfl_xor_sync(0xffffffffu, acc, off);
        if (lane == 0) {
            float s = read_mask(mbase, moff + t, mmode) ? (acc + bb) : NEGV;
            keys[t] = ((unsigned long long)fkey(s) << 32) | (unsigned int)(~t);
        }
    }
    __syncthreads();

    for (int size = 2; size <= L; size <<= 1) {
        for (int stride = size >> 1; stride > 0; stride >>= 1) {
            if (tid < L) {
                int j = tid ^ stride;
                if (j > tid) {
                    bool descend = ((tid & size) == 0);
                    unsigned long long a = keys[tid], c = keys[j];
                    if (descend ? (a < c) : (a > c)) { keys[tid] = c; keys[j] = a; }
                }
            }
            __syncthreads();
        }
    }

    if (isCand) {
        int cnt = 0;
        for (int j = tid; j < k; j += 512) {
            int t = (int)(~(unsigned int)keys[j]);
            if (read_mask(mbase, moff + t, mmode)) cnt++;
        }
        if (cnt) atomicAdd(&s_count, cnt);
        __syncthreads();
        if (tid == 0) g_candValid[row] = s_count;
        __half2* dst = (__half2*)(g_candSel + (size_t)row * KQ * DD);
        for (int e = tid; e < KQ * (DD/2); e += 512) {
            int j = e >> 6, d = e & 63;
            int t = (int)(~(unsigned int)keys[j]);
            float2 v = ((const float2*)(rep + t * DD))[d];
            dst[e] = __floats2half2_rn(v.x, v.y);
        }
    } else {
        for (int j = tid; j < k; j += 512) {
            int t = (int)(~(unsigned int)keys[j]);
            g_ctxtMask[row * KK + j] = read_mask(mbase, moff + t, mmode) ? 1.0f : 0.0f;
        }
        __half2* dst = (__half2*)(g_ctxtSel + (size_t)row * KK * DD);
        for (int e = tid; e < KK * (DD/2); e += 512) {
            int j = e >> 6, d = e & 63;
            int t = (int)(~(unsigned int)keys[j]);
            float2 v = ((const float2*)(rep + t * DD))[d];
            dst[e] = __floats2half2_rn(v.x, v.y);
        }
    }
}

// ---------------------------------------------------------------------------
// Kernel 2: one block per (bq, kk-quad). cand staged once; ctxt double-buffered
// via cp.async groups, prefetch overlapped with previous iteration's GEMM.
// Transposed epilogue: D[128 ctxt, 64 cand], column-masked row max + mean.
// ---------------------------------------------------------------------------
__device__ __forceinline__ void atomicMaxF(float* addr, float v) {
    if (v >= 0.f) atomicMax((int*)addr, __float_as_int(v));
    else          atomicMin((unsigned int*)addr, __float_as_uint(v));
}
__device__ __forceinline__ void ldsm_x4(unsigned int* r, unsigned int saddr) {
    asm volatile("ldmatrix.sync.aligned.m8n8.x4.shared.b16 {%0,%1,%2,%3}, [%4];"
                 : "=r"(r[0]), "=r"(r[1]), "=r"(r[2]), "=r"(r[3]) : "r"(saddr));
}
__device__ __forceinline__ void cp16(unsigned int dst, const void* src) {
    asm volatile("cp.async.cg.shared.global [%0], [%1], 16;\n" :: "r"(dst), "l"(src));
}
__device__ __forceinline__ void mma16816(float* C, const unsigned int* A,
                                         unsigned int b0, unsigned int b1) {
    asm volatile(
        "mma.sync.aligned.m16n8k16.row.col.f32.f16.f16.f32 "
        "{%0,%1,%2,%3}, {%4,%5,%6,%7}, {%8,%9}, {%0,%1,%2,%3};\n"
        : "+f"(C[0]), "+f"(C[1]), "+f"(C[2]), "+f"(C[3])
        : "r"(A[0]), "r"(A[1]), "r"(A[2]), "r"(A[3]), "r"(b0), "r"(b1));
}

__global__ __launch_bounds__(256, 2) void gemm_max_mean_kernel(float* __restrict__ out)
{
    extern __shared__ __align__(16) unsigned char smraw[];
    __half* As  = (__half*)smraw;                        // 2 buffers: 128 x PADD each
    __half* Bsh = (__half*)smraw + SM_B_H;               // cand: 64 x PADD
    float*  rowmax = (float*)(smraw + SM_RM_B);          // 128
    __shared__ float sAccV, sAccM;

    int tid  = threadIdx.x;
    int lane = tid & 31, wid = tid >> 5;
    int wm = wid >> 1;            // 0..3 : ctxt rows [wm*32, +32)
    int wn = wid & 1;             // 0..1 : cand cols [wn*32, +32)
    int blk = blockIdx.x;
    int bq  = blk >> 2;           // 4 kk per block
    int kk0 = (blk & 3) * 4;
    int b   = bq >> 5;            // NQ = 32

    unsigned int AsAddr = (unsigned int)__cvta_generic_to_shared(As);
    unsigned int BsAddr = (unsigned int)__cvta_generic_to_shared(Bsh);
    const size_t ctxtBase = (size_t)(b * NK) * KK * DD;

    // G0: cand (64 rows) + ctxt[kk0] into buffer 0
    {
        const __half* Bg = g_candSel + (size_t)bq * KQ * DD;
        for (int i = tid; i < 64 * 16; i += 256) {
            int r = i >> 4, seg = i & 15;
            cp16(BsAddr + (r * PADD + seg * 8) * 2, &Bg[r * DD + seg * 8]);
        }
        const __half* Ag = g_ctxtSel + ctxtBase + (size_t)kk0 * KK * DD;
        for (int i = tid; i < 128 * 16; i += 256) {
            int r = i >> 4, seg = i & 15;
            cp16(AsAddr + (r * PADD + seg * 8) * 2, &Ag[r * DD + seg * 8]);
        }
        asm volatile("cp.async.commit_group;\n");
    }
    int nvalid = g_candValid[bq];

    // ldmatrix lane addressing (buffer 0 base; buffer 1 = +ABUF_H*2 bytes)
    int t8   = lane >> 3;
    int rsub = lane & 7;
    unsigned int aAddr0 = (unsigned int)__cvta_generic_to_shared(
        &As[(wm * 32 + (t8 & 1) * 8 + rsub) * PADD + (t8 >> 1) * 8]);
    unsigned int bAddr = (unsigned int)__cvta_generic_to_shared(
        &Bsh[(wn * 32 + (t8 & 1) * 8 + rsub) * PADD + (t8 >> 1) * 8]);
    const unsigned int mtStep = 16 * PADD * 2;
    int g = lane >> 2;
    int cpair = (lane & 3) * 2;

    #pragma unroll 1
    for (int it = 0; it < 4; it++) {
        int p = it & 1;
        int kk = kk0 + it;

        if (tid < 128) rowmax[tid] = NEGV;
        if (tid == 0) { sAccV = 0.f; sAccM = 0.f; }

        // prefetch next ctxt tile into buffer p^1
        if (it < 3) {
            const __half* Ag = g_ctxtSel + ctxtBase + (size_t)(kk + 1) * KK * DD;
            unsigned int dstA = AsAddr + (p ^ 1) * (ABUF_H * 2);
            for (int i = tid; i < 128 * 16; i += 256) {
                int r = i >> 4, seg = i & 15;
                cp16(dstA + (r * PADD + seg * 8) * 2, &Ag[r * DD + seg * 8]);
            }
            asm volatile("cp.async.commit_group;\n");
            asm volatile("cp.async.wait_group 1;\n");
        } else {
            asm volatile("cp.async.wait_group 0;\n");
        }
        __syncthreads();

        unsigned int aBase = aAddr0 + p * (ABUF_H * 2);

        float C[2][4][4];
        #pragma unroll
        for (int mt = 0; mt < 2; mt++)
            #pragma unroll
            for (int np = 0; np < 4; np++)
                #pragma unroll
                for (int j = 0; j < 4; j++) C[mt][np][j] = 0.f;

        unsigned int aF[2][2][4], bF[2][2][4];
        ldsm_x4(aF[0][0], aBase);
        ldsm_x4(aF[0][1], aBase + mtStep);
        ldsm_x4(bF[0][0], bAddr);
        ldsm_x4(bF[0][1], bAddr + mtStep);

        #pragma unroll
        for (int ks = 0; ks < 8; ks++) {
            int cur = ks & 1, nxt = cur ^ 1;
            if (ks < 7) {
                unsigned int off = (ks + 1) * 32;
                ldsm_x4(aF[nxt][0], aBase + off);
                ldsm_x4(aF[nxt][1], aBase + mtStep + off);
                ldsm_x4(bF[nxt][0], bAddr + off);
                ldsm_x4(bF[nxt][1], bAddr + mtStep + off);
            }
            #pragma unroll
            for (int mt = 0; mt < 2; mt++) {
                #pragma unroll
                for (int pp = 0; pp < 2; pp++) {
                    mma16816(C[mt][2*pp],   aF[cur][mt], bF[cur][pp][0], bF[cur][pp][2]);
                    mma16816(C[mt][2*pp+1], aF[cur][mt], bF[cur][pp][1], bF[cur][pp][3]);
                }
            }
        }

        // register column-masked row max (cand cols >= nvalid excluded)
        #pragma unroll
        for (int mt = 0; mt < 2; mt++) {
            float m0 = NEGV, m1 = NEGV;
            #pragma unroll
            for (int np = 0; np < 4; np++) {
                int col = wn * 32 + np * 8 + cpair;
                bool v0 = (col < nvalid), v1 = (col + 1 < nvalid);
                m0 = fmaxf(m0, fmaxf(v0 ? C[mt][np][0] : NEGV, v1 ? C[mt][np][1] : NEGV));
                m1 = fmaxf(m1, fmaxf(v0 ? C[mt][np][2] : NEGV, v1 ? C[mt][np][3] : NEGV));
            }
            #pragma unroll
            for (int off = 1; off < 4; off <<= 1) {
                m0 = fmaxf(m0, __shfl_xor_sync(0xffffffffu, m0, off));
                m1 = fmaxf(m1, __shfl_xor_sync(0xffffffffu, m1, off));
            }
            if ((lane & 3) == 0) {
                int r = wm * 32 + mt * 16 + g;
                atomicMaxF(&rowmax[r],     m0);
                atomicMaxF(&rowmax[r + 8], m1);
            }
        }
        __syncthreads();

        // masked mean over 128 ctxt tokens
        if (tid < 128) {
            float m = g_ctxtMask[(b * NK + kk) * KK + tid];
            float v = rowmax[tid] * m;
            #pragma unroll
            for (int off = 16; off; off >>= 1) {
                v += __shfl_xor_sync(0xffffffffu, v, off);
                m += __shfl_xor_sync(0xffffffffu, m, off);
            }
            if (lane == 0) { atomicAdd(&sAccV, v); atomicAdd(&sAccM, m); }
        }
        __syncthreads();
        if (tid == 0) out[bq * NK + kk] = sAccV / sAccM;
    }
}

// ---------------------------------------------------------------------------
extern "C" void kernel_launch(void* const* d_in, const int* in_sizes, int n_in,
                              void* d_out, int out_size)
{
    const float*         cand  = (const float*)d_in[0];
    const float*         ctxt  = (const float*)d_in[1];
    const unsigned char* mcand = (const unsigned char*)d_in[2];
    const unsigned char* mctxt = (const unsigned char*)d_in[3];
    const float*         W     = (const float*)d_in[4];
    const float*         bptr  = (const float*)d_in[5];
    float* out = (float*)d_out;

    cudaFuncSetAttribute(gemm_max_mean_kernel,
                         cudaFuncAttributeMaxDynamicSharedMemorySize, SMEM_K2);

    select_gather_kernel<<<BB*NQ + BB*NK, 512>>>(cand, ctxt, mcand, mctxt, W, bptr);
    gemm_max_mean_kernel<<<BB*NQ*4, 256, SMEM_K2>>>(out);
}

// round 10
// speedup vs baseline: 1.0903x; 1.0903x over previous
#include <cuda_runtime.h>
#include <cuda_fp16.h>
#include <cstdint>

#define BB 8
#define NQ 32
#define LQ 128
#define NK 16
#define LK 256
#define DD 128
#define KQ 64
#define KK 128
#define NEGV -99999.0f
#define PADD 136 // halfs per smem row (16B pad per 256B row -> conflict-free ldmatrix)

// K2 smem: A(ctxt) 128 x PADD + B(cand) 64 x PADD halfs + rowmax[128] floats
#define SMEM_K2 ((128 + 64) * PADD * 2 + 128 * 4)

__device__ __align__(16) __half g_candSel[BB*NQ*KQ*DD];   // [token][dim]
__device__ __align__(16) __half g_ctxtSel[BB*NK*KK*DD];   // [token][dim]
__device__ int   g_candValid[BB*NQ];
__device__ float g_ctxtMask[BB*NK*KK];

__device__ __forceinline__ unsigned int fkey(float f) {
    unsigned int u = __float_as_uint(f);
    return (u & 0x80000000u) ? ~u : (u | 0x80000000u);
}
__device__ __forceinline__ int mask_mode(const unsigned char* m) {
    const unsigned int* w = (const unsigned int*)m;
    #pragma unroll
    for (int i = 0; i < 4; i++) {
        unsigned int v = w[i];
        if (v == 0x3F800000u) return 2;
        if (v > 1u) return 0;
    }
    return 1;
}
__device__ __forceinline__ bool read_mask(const unsigned char* m, int i, int mode) {
    if (mode == 0) return m[i] != 0;
    if (mode == 1) return ((const int*)m)[i] != 0;
    return ((const float*)m)[i] != 0.0f;
}

// ---------------------------------------------------------------------------
// Kernel 1: scores -> bitonic top-k -> gather to fp16 scratch (512 threads)
// ---------------------------------------------------------------------------
__global__ __launch_bounds__(512) void select_gather_kernel(
    const float* __restrict__ cand, const float* __restrict__ ctxt,
    const unsigned char* __restrict__ mcand, const unsigned char* __restrict__ mctxt,
    const float* __restrict__ W, const float* __restrict__ bptr)
{
    __shared__ __align__(16) float Ws[DD];
    __shared__ unsigned long long keys[256];
    __shared__ int s_count;

    int tid = threadIdx.x;
    bool isCand = (blockIdx.x < BB*NQ);
    int row = isCand ? blockIdx.x : (blockIdx.x - BB*NQ);
    int L = isCand ? LQ : LK;
    int k = L >> 1;
    const float* rep = isCand ? (cand + (size_t)row * LQ * DD)
                              : (ctxt + (size_t)row * LK * DD);
    const unsigned char* mbase = isCand ? mcand : mctxt;
    int mmode = mask_mode(mbase);
    int moff  = row * L;

    if (tid < DD) Ws[tid] = W[tid];
    if (tid == 0) s_count = 0;
    __syncthreads();

    float bb = bptr[0];
    int wid = tid >> 5, lane = tid & 31;

    for (int t = wid; t < L; t += 16) {
        float4 v  = ((const float4*)(rep + t * DD))[lane];
        float4 w4 = ((const float4*)Ws)[lane];
        float acc = v.x*w4.x + v.y*w4.y + v.z*w4.z + v.w*w4.w;
        #pragma unroll
        for (int off = 16; off; off >>= 1) acc += __shfl_xor_sync(0xffffffffu, acc, off);
        if (lane == 0) {
            float s = read_mask(mbase, moff + t, mmode) ? (acc + bb) : NEGV;
            keys[t] = ((unsigned long long)fkey(s) << 32) | (unsigned int)(~t);
        }
    }
    __syncthreads();

    for (int size = 2; size <= L; size <<= 1) {
        for (int stride = size >> 1; stride > 0; stride >>= 1) {
            if (tid < L) {
                int j = tid ^ stride;
                if (j > tid) {
                    bool descend = ((tid & size) == 0);
                    unsigned long long a = keys[tid], c = keys[j];
                    if (descend ? (a < c) : (a > c)) { keys[tid] = c; keys[j] = a; }
                }
            }
            __syncthreads();
        }
    }

    if (isCand) {
        int cnt = 0;
        for (int j = tid; j < k; j += 512) {
            int t = (int)(~(unsigned int)keys[j]);
            if (read_mask(mbase, moff + t, mmode)) cnt++;
        }
        if (cnt) atomicAdd(&s_count, cnt);
        __syncthreads();
        if (tid == 0) g_candValid[row] = s_count;
        __half2* dst = (__half2*)(g_candSel + (size_t)row * KQ * DD);
        for (int e = tid; e < KQ * (DD/2); e += 512) {
            int j = e >> 6, d = e & 63;
            int t = (int)(~(unsigned int)keys[j]);
            float2 v = ((const float2*)(rep + t * DD))[d];
            dst[e] = __floats2half2_rn(v.x, v.y);
        }
    } else {
        for (int j = tid; j < k; j += 512) {
            int t = (int)(~(unsigned int)keys[j]);
            g_ctxtMask[row * KK + j] = read_mask(mbase, moff + t, mmode) ? 1.0f : 0.0f;
        }
        __half2* dst = (__half2*)(g_ctxtSel + (size_t)row * KK * DD);
        for (int e = tid; e < KK * (DD/2); e += 512) {
            int j = e >> 6, d = e & 63;
            int t = (int)(~(unsigned int)keys[j]);
            float2 v = ((const float2*)(rep + t * DD))[d];
            dst[e] = __floats2half2_rn(v.x, v.y);
        }
    }
}

// ---------------------------------------------------------------------------
// Kernel 2: one block per (bq, kk). Transposed D[128 ctxt, 64 cand].
// Single-buffer fragments, 4 CTAs/SM target (cross-warp latency hiding).
// ---------------------------------------------------------------------------
__device__ __forceinline__ void atomicMaxF(float* addr, float v) {
    if (v >= 0.f) atomicMax((int*)addr, __float_as_int(v));
    else          atomicMin((unsigned int*)addr, __float_as_uint(v));
}
__device__ __forceinline__ void ldsm_x4(unsigned int* r, unsigned int saddr) {
    asm volatile("ldmatrix.sync.aligned.m8n8.x4.shared.b16 {%0,%1,%2,%3}, [%4];"
                 : "=r"(r[0]), "=r"(r[1]), "=r"(r[2]), "=r"(r[3]) : "r"(saddr));
}
__device__ __forceinline__ void cp16(unsigned int dst, const void* src) {
    asm volatile("cp.async.cg.shared.global [%0], [%1], 16;\n" :: "r"(dst), "l"(src));
}
__device__ __forceinline__ void mma16816(float* C, const unsigned int* A,
                                         unsigned int b0, unsigned int b1) {
    asm volatile(
        "mma.sync.aligned.m16n8k16.row.col.f32.f16.f16.f32 "
        "{%0,%1,%2,%3}, {%4,%5,%6,%7}, {%8,%9}, {%0,%1,%2,%3};\n"
        : "+f"(C[0]), "+f"(C[1]), "+f"(C[2]), "+f"(C[3])
        : "r"(A[0]), "r"(A[1]), "r"(A[2]), "r"(A[3]), "r"(b0), "r"(b1));
}

__global__ __launch_bounds__(256, 4) void gemm_max_mean_kernel(float* __restrict__ out)
{
    extern __shared__ __align__(16) unsigned char smraw[];
    __half* As  = (__half*)smraw;                       // ctxt: 128 x PADD
    __half* Bsh = (__half*)smraw + 128 * PADD;          // cand: 64 x PADD
    float*  rowmax = (float*)((__half*)smraw + (128 + 64) * PADD);  // 128
    __shared__ float sAccV, sAccM;

    int tid  = threadIdx.x;
    int lane = tid & 31, wid = tid >> 5;
    int wm = wid >> 1;            // 0..3 : ctxt rows [wm*32, +32)
    int wn = wid & 1;             // 0..1 : cand cols [wn*32, +32)
    int blk = blockIdx.x;
    int bq = blk >> 4;            // NK = 16
    int kk = blk & 15;
    int b  = bq >> 5;             // NQ = 32
    int g  = lane >> 2;
    int cpair = (lane & 3) * 2;

    // Stage A = ctxt (128x128), B = cand (64x128) via cp.async
    {
        const __half* Ag = g_ctxtSel + ((size_t)(b * NK + kk)) * KK * DD;
        unsigned int AsAddr = (unsigned int)__cvta_generic_to_shared(As);
        for (int i = tid; i < 128 * 16; i += 256) {
            int r = i >> 4, seg = i & 15;
            cp16(AsAddr + (r * PADD + seg * 8) * 2, &Ag[r * DD + seg * 8]);
        }
        const __half* Bg = g_candSel + (size_t)bq * KQ * DD;
        unsigned int BsAddr = (unsigned int)__cvta_generic_to_shared(Bsh);
        for (int i = tid; i < 64 * 16; i += 256) {
            int r = i >> 4, seg = i & 15;
            cp16(BsAddr + (r * PADD + seg * 8) * 2, &Bg[r * DD + seg * 8]);
        }
        asm volatile("cp.async.commit_group;\n");
    }
    if (tid < 128) rowmax[tid] = NEGV;
    if (tid == 0) { sAccV = 0.f; sAccM = 0.f; }
    int nvalid = g_candValid[bq];
    asm volatile("cp.async.wait_group 0;\n");
    __syncthreads();

    // ldmatrix lane addressing
    int t8   = lane >> 3;
    int rsub = lane & 7;
    unsigned int aAddr = (unsigned int)__cvta_generic_to_shared(
        &As[(wm * 32 + (t8 & 1) * 8 + rsub) * PADD + (t8 >> 1) * 8]);
    unsigned int bAddr = (unsigned int)__cvta_generic_to_shared(
        &Bsh[(wn * 32 + (t8 & 1) * 8 + rsub) * PADD + (t8 >> 1) * 8]);
    const unsigned int mtStep = 16 * PADD * 2;

    float C[2][4][4];
    #pragma unroll
    for (int mt = 0; mt < 2; mt++)
        #pragma unroll
        for (int np = 0; np < 4; np++)
            #pragma unroll
            for (int j = 0; j < 4; j++) C[mt][np][j] = 0.f;

    #pragma unroll
    for (int ks = 0; ks < 8; ks++) {
        unsigned int off = ks * 32;
        unsigned int aF0[4], aF1[4], bF0[4], bF1[4];
        ldsm_x4(aF0, aAddr + off);
        ldsm_x4(aF1, aAddr + mtStep + off);
        ldsm_x4(bF0, bAddr + off);
        ldsm_x4(bF1, bAddr + mtStep + off);
        mma16816(C[0][0], aF0, bF0[0], bF0[2]);
        mma16816(C[0][1], aF0, bF0[1], bF0[3]);
        mma16816(C[0][2], aF0, bF1[0], bF1[2]);
        mma16816(C[0][3], aF0, bF1[1], bF1[3]);
        mma16816(C[1][0], aF1, bF0[0], bF0[2]);
        mma16816(C[1][1], aF1, bF0[1], bF0[3]);
        mma16816(C[1][2], aF1, bF1[0], bF1[2]);
        mma16816(C[1][3], aF1, bF1[1], bF1[3]);
    }

    // register column-masked row max (cand cols >= nvalid excluded)
    #pragma unroll
    for (int mt = 0; mt < 2; mt++) {
        float m0 = NEGV, m1 = NEGV;
        #pragma unroll
        for (int np = 0; np < 4; np++) {
            int col = wn * 32 + np * 8 + cpair;
            bool v0 = (col < nvalid), v1 = (col + 1 < nvalid);
            m0 = fmaxf(m0, fmaxf(v0 ? C[mt][np][0] : NEGV, v1 ? C[mt][np][1] : NEGV));
            m1 = fmaxf(m1, fmaxf(v0 ? C[mt][np][2] : NEGV, v1 ? C[mt][np][3] : NEGV));
        }
        #pragma unroll
        for (int off = 1; off < 4; off <<= 1) {
            m0 = fmaxf(m0, __shfl_xor_sync(0xffffffffu, m0, off));
            m1 = fmaxf(m1, __shfl_xor_sync(0xffffffffu, m1, off));
        }
        if ((lane & 3) == 0) {
            int r = wm * 32 + mt * 16 + g;
            atomicMaxF(&rowmax[r],     m0);
            atomicMaxF(&rowmax[r + 8], m1);
        }
    }
    __syncthreads();

    // masked mean over 128 ctxt tokens (rows)
    if (tid < 128) {
        float m = g_ctxtMask[(b * NK + kk) * KK + tid];
        float v = rowmax[tid] * m;
        #pragma unroll
        for (int off = 16; off; off >>= 1) {
            v += __shfl_xor_sync(0xffffffffu, v, off);
            m += __shfl_xor_sync(0xffffffffu, m, off);
        }
        if (lane == 0) { atomicAdd(&sAccV, v); atomicAdd(&sAccM, m); }
    }
    __syncthreads();
    if (tid == 0) out[bq * NK + kk] = sAccV / sAccM;
}

// ---------------------------------------------------------------------------
extern "C" void kernel_launch(void* const* d_in, const int* in_sizes, int n_in,
                              void* d_out, int out_size)
{
    const float*         cand  = (const float*)d_in[0];
    const float*         ctxt  = (const float*)d_in[1];
    const unsigned char* mcand = (const unsigned char*)d_in[2];
    const unsigned char* mctxt = (const unsigned char*)d_in[3];
    const float*         W     = (const float*)d_in[4];
    const float*         bptr  = (const float*)d_in[5];
    float* out = (float*)d_out;

    cudaFuncSetAttribute(gemm_max_mean_kernel,
                         cudaFuncAttributeMaxDynamicSharedMemorySize, SMEM_K2);

    select_gather_kernel<<<BB*NQ + BB*NK, 512>>>(cand, ctxt, mcand, mctxt, W, bptr);
    gemm_max_mean_kernel<<<BB*NQ*NK, 256, SMEM_K2>>>(out);
}

// round 12
// speedup vs baseline: 1.1499x; 1.0546x over previous
#include <cuda_runtime.h>
#include <cuda_fp16.h>
#include <cstdint>

#define BB 8
#define NQ 32
#define LQ 128
#define NK 16
#define LK 256
#define DD 128
#define KQ 64
#define KK 128
#define NEGV -99999.0f
#define PADD 136 // halfs per smem row (16B pad per 256B row -> conflict-free ldmatrix)

// K2 smem: A(ctxt) 128 x PADD + B(cand) 64 x PADD halfs + rowmax[128] floats
#define SMEM_K2 ((128 + 64) * PADD * 2 + 128 * 4)

__device__ __align__(16) __half g_candSel[BB*NQ*KQ*DD];   // [token][dim]
__device__ __align__(16) __half g_ctxtSel[BB*NK*KK*DD];   // [token][dim]
__device__ int   g_candValid[BB*NQ];
__device__ float g_ctxtMask[BB*NK*KK];

__device__ __forceinline__ unsigned int fkey(float f) {
    unsigned int u = __float_as_uint(f);
    return (u & 0x80000000u) ? ~u : (u | 0x80000000u);
}
__device__ __forceinline__ int mask_mode(const unsigned char* m) {
    const unsigned int* w = (const unsigned int*)m;
    #pragma unroll
    for (int i = 0; i < 4; i++) {
        unsigned int v = w[i];
        if (v == 0x3F800000u) return 2;
        if (v > 1u) return 0;
    }
    return 1;
}
__device__ __forceinline__ bool read_mask(const unsigned char* m, int i, int mode) {
    if (mode == 0) return m[i] != 0;
    if (mode == 1) return ((const int*)m)[i] != 0;
    return ((const float*)m)[i] != 0.0f;
}

// ---------------------------------------------------------------------------
// Kernel 1: scores (4-way batched MLP) -> bitonic top-k -> float4 gather
// ---------------------------------------------------------------------------
__global__ __launch_bounds__(512) void select_gather_kernel(
    const float* __restrict__ cand, const float* __restrict__ ctxt,
    const unsigned char* __restrict__ mcand, const unsigned char* __restrict__ mctxt,
    const float* __restrict__ W, const float* __restrict__ bptr)
{
    __shared__ __align__(16) float Ws[DD];
    __shared__ unsigned long long keys[256];
    __shared__ int s_count;

    int tid = threadIdx.x;
    bool isCand = (blockIdx.x < BB*NQ);
    int row = isCand ? blockIdx.x : (blockIdx.x - BB*NQ);
    int L = isCand ? LQ : LK;
    int k = L >> 1;
    const float* rep = isCand ? (cand + (size_t)row * LQ * DD)
                              : (ctxt + (size_t)row * LK * DD);
    const unsigned char* mbase = isCand ? mcand : mctxt;
    int mmode = mask_mode(mbase);
    int moff  = row * L;

    if (tid < DD) Ws[tid] = W[tid];
    if (tid == 0) s_count = 0;
    __syncthreads();

    float bb = bptr[0];
    int wid = tid >> 5, lane = tid & 31;

    // scores: 16 warps, 4 tokens per warp per round (independent loads -> MLP=4)
    {
        float4 w4 = ((const float4*)Ws)[lane];
        for (int t0 = wid; t0 < L; t0 += 64) {
            float acc[4];
            #pragma unroll
            for (int j = 0; j < 4; j++) {
                float4 v = ((const float4*)(rep + (t0 + j * 16) * DD))[lane];
                acc[j] = v.x*w4.x + v.y*w4.y + v.z*w4.z + v.w*w4.w;
            }
            #pragma unroll
            for (int off = 16; off; off >>= 1) {
                #pragma unroll
                for (int j = 0; j < 4; j++)
                    acc[j] += __shfl_xor_sync(0xffffffffu, acc[j], off);
            }
            if (lane == 0) {
                #pragma unroll
                for (int j = 0; j < 4; j++) {
                    int t = t0 + j * 16;
                    float s = read_mask(mbase, moff + t, mmode) ? (acc[j] + bb) : NEGV;
                    keys[t] = ((unsigned long long)fkey(s) << 32) | (unsigned int)(~t);
                }
            }
        }
    }
    __syncthreads();

    // bitonic sort, descending
    for (int size = 2; size <= L; size <<= 1) {
        for (int stride = size >> 1; stride > 0; stride >>= 1) {
            if (tid < L) {
                int j = tid ^ stride;
                if (j > tid) {
                    bool descend = ((tid & size) == 0);
                    unsigned long long a = keys[tid], c = keys[j];
                    if (descend ? (a < c) : (a > c)) { keys[tid] = c; keys[j] = a; }
                }
            }
            __syncthreads();
        }
    }

    if (isCand) {
        int cnt = 0;
        for (int j = tid; j < k; j += 512) {
            int t = (int)(~(unsigned int)keys[j]);
            if (read_mask(mbase, moff + t, mmode)) cnt++;
        }
        if (cnt) atomicAdd(&s_count, cnt);
        __syncthreads();
        if (tid == 0) g_candValid[row] = s_count;
    } else {
        for (int j = tid; j < k; j += 512) {
            int t = (int)(~(unsigned int)keys[j]);
            g_ctxtMask[row * KK + j] = read_mask(mbase, moff + t, mmode) ? 1.0f : 0.0f;
        }
    }

    // gather: 32B read -> 16B write per iteration
    __half* dst = isCand ? (g_candSel + (size_t)row * KQ * DD)
                         : (g_ctxtSel + (size_t)row * KK * DD);
    for (int e = tid; e < k * 16; e += 512) {
        int j = e >> 4, c = e & 15;
        int t = (int)(~(unsigned int)keys[j]);
        const float4* s = (const float4*)(rep + t * DD + c * 8);
        float4 v0 = s[0], v1 = s[1];
        int4 pk;
        __half2* ph = (__half2*)&pk;
        ph[0] = __floats2half2_rn(v0.x, v0.y);
        ph[1] = __floats2half2_rn(v0.z, v0.w);
        ph[2] = __floats2half2_rn(v1.x, v1.y);
        ph[3] = __floats2half2_rn(v1.z, v1.w);
        *(int4*)&dst[j * DD + c * 8] = pk;
    }
}

// ---------------------------------------------------------------------------
// Kernel 2: one block per (bq, kk). Transposed D[128 ctxt, 64 cand].
// Single-buffer fragments, 4 CTAs/SM (unchanged from R10).
// ---------------------------------------------------------------------------
__device__ __forceinline__ void atomicMaxF(float* addr, float v) {
    if (v >= 0.f) atomicMax((int*)addr, __float_as_int(v));
    else          atomicMin((unsigned int*)addr, __float_as_uint(v));
}
__device__ __forceinline__ void ldsm_x4(unsigned int* r, unsigned int saddr) {
    asm volatile("ldmatrix.sync.aligned.m8n8.x4.shared.b16 {%0,%1,%2,%3}, [%4];"
                 : "=r"(r[0]), "=r"(r[1]), "=r"(r[2]), "=r"(r[3]) : "r"(saddr));
}
__device__ __forceinline__ void cp16(unsigned int dst, const void* src) {
    asm volatile("cp.async.cg.shared.global [%0], [%1], 16;\n" :: "r"(dst), "l"(src));
}
__device__ __forceinline__ void mma16816(float* C, const unsigned int* A,
                                         unsigned int b0, unsigned int b1) {
    asm volatile(
        "mma.sync.aligned.m16n8k16.row.col.f32.f16.f16.f32 "
        "{%0,%1,%2,%3}, {%4,%5,%6,%7}, {%8,%9}, {%0,%1,%2,%3};\n"
        : "+f"(C[0]), "+f"(C[1]), "+f"(C[2]), "+f"(C[3])
        : "r"(A[0]), "r"(A[1]), "r"(A[2]), "r"(A[3]), "r"(b0), "r"(b1));
}

__global__ __launch_bounds__(256, 4) void gemm_max_mean_kernel(float* __restrict__ out)
{
    extern __shared__ __align__(16) unsigned char smraw[];
    __half* As  = (__half*)smraw;                       // ctxt: 128 x PADD
    __half* Bsh = (__half*)smraw + 128 * PADD;          // cand: 64 x PADD
    float*  rowmax = (float*)((__half*)smraw + (128 + 64) * PADD);  // 128
    __shared__ float sAccV, sAccM;

    int tid  = threadIdx.x;
    int lane = tid & 31, wid = tid >> 5;
    int wm = wid >> 1;
    int wn = wid & 1;
    int blk = blockIdx.x;
    int bq = blk >> 4;
    int kk = blk & 15;
    int b  = bq >> 5;
    int g  = lane >> 2;
    int cpair = (lane & 3) * 2;

    {
        const __half* Ag = g_ctxtSel + ((size_t)(b * NK + kk)) * KK * DD;
        unsigned int AsAddr = (unsigned int)__cvta_generic_to_shared(As);
        for (int i = tid; i < 128 * 16; i += 256) {
            int r = i >> 4, seg = i & 15;
            cp16(AsAddr + (r * PADD + seg * 8) * 2, &Ag[r * DD + seg * 8]);
        }
        const __half* Bg = g_candSel + (size_t)bq * KQ * DD;
        unsigned int BsAddr = (unsigned int)__cvta_generic_to_shared(Bsh);
        for (int i = tid; i < 64 * 16; i += 256) {
            int r = i >> 4, seg = i & 15;
            cp16(BsAddr + (r * PADD + seg * 8) * 2, &Bg[r * DD + seg * 8]);
        }
        asm volatile("cp.async.commit_group;\n");
    }
    if (tid < 128) rowmax[tid] = NEGV;
    if (tid == 0) { sAccV = 0.f; sAccM = 0.f; }
    int nvalid = g_candValid[bq];
    asm volatile("cp.async.wait_group 0;\n");
    __syncthreads();

    int t8   = lane >> 3;
    int rsub = lane & 7;
    unsigned int aAddr = (unsigned int)__cvta_generic_to_shared(
        &As[(wm * 32 + (t8 & 1) * 8 + rsub) * PADD + (t8 >> 1) * 8]);
    unsigned int bAddr = (unsigned int)__cvta_generic_to_shared(
        &Bsh[(wn * 32 + (t8 & 1) * 8 + rsub) * PADD + (t8 >> 1) * 8]);
    const unsigned int mtStep = 16 * PADD * 2;

    float C[2][4][4];
    #pragma unroll
    for (int mt = 0; mt < 2; mt++)
        #pragma unroll
        for (int np = 0; np < 4; np++)
            #pragma unroll
            for (int j = 0; j < 4; j++) C[mt][np][j] = 0.f;

    #pragma unroll
    for (int ks = 0; ks < 8; ks++) {
        unsigned int off = ks * 32;
        unsigned int aF0[4], aF1[4], bF0[4], bF1[4];
        ldsm_x4(aF0, aAddr + off);
        ldsm_x4(aF1, aAddr + mtStep + off);
        ldsm_x4(bF0, bAddr + off);
        ldsm_x4(bF1, bAddr + mtStep + off);
        mma16816(C[0][0], aF0, bF0[0], bF0[2]);
        mma16816(C[0][1], aF0, bF0[1], bF0[3]);
        mma16816(C[0][2], aF0, bF1[0], bF1[2]);
        mma16816(C[0][3], aF0, bF1[1], bF1[3]);
        mma16816(C[1][0], aF1, bF0[0], bF0[2]);
        mma16816(C[1][1], aF1, bF0[1], bF0[3]);
        mma16816(C[1][2], aF1, bF1[0], bF1[2]);
        mma16816(C[1][3], aF1, bF1[1], bF1[3]);
    }

    #pragma unroll
    for (int mt = 0; mt < 2; mt++) {
        float m0 = NEGV, m1 = NEGV;
        #pragma unroll
        for (int np = 0; np < 4; np++) {
            int col = wn * 32 + np * 8 + cpair;
            bool v0 = (col < nvalid), v1 = (col + 1 < nvalid);
            m0 = fmaxf(m0, fmaxf(v0 ? C[mt][np][0] : NEGV, v1 ? C[mt][np][1] : NEGV));
            m1 = fmaxf(m1, fmaxf(v0 ? C[mt][np][2] : NEGV, v1 ? C[mt][np][3] : NEGV));
        }
        #pragma unroll
        for (int off = 1; off < 4; off <<= 1) {
            m0 = fmaxf(m0, __shfl_xor_sync(0xffffffffu, m0, off));
            m1 = fmaxf(m1, __shfl_xor_sync(0xffffffffu, m1, off));
        }
        if ((lane & 3) == 0) {
            int r = wm * 32 + mt * 16 + g;
            atomicMaxF(&rowmax[r],     m0);
            atomicMaxF(&rowmax[r + 8], m1);
        }
    }
    __syncthreads();

    if (tid < 128) {
        float m = g_ctxtMask[(b * NK + kk) * KK + tid];
        float v = rowmax[tid] * m;
        #pragma unroll
        for (int off = 16; off; off >>= 1) {
            v += __shfl_xor_sync(0xffffffffu, v, off);
            m += __shfl_xor_sync(0xffffffffu, m, off);
        }
        if (lane == 0) { atomicAdd(&sAccV, v); atomicAdd(&sAccM, m); }
    }
    __syncthreads();
    if (tid == 0) out[bq * NK + kk] = sAccV / sAccM;
}

// ---------------------------------------------------------------------------
extern "C" void kernel_launch(void* const* d_in, const int* in_sizes, int n_in,
                              void* d_out, int out_size)
{
    const float*         cand  = (const float*)d_in[0];
    const float*         ctxt  = (const float*)d_in[1];
    const unsigned char* mcand = (const unsigned char*)d_in[2];
    const unsigned char* mctxt = (const unsigned char*)d_in[3];
    const float*         W     = (const float*)d_in[4];
    const float*         bptr  = (const float*)d_in[5];
    float* out = (float*)d_out;

    cudaFuncSetAttribute(gemm_max_mean_kernel,
                         cudaFuncAttributeMaxDynamicSharedMemorySize, SMEM_K2);

    select_gather_kernel<<<BB*NQ + BB*NK, 512>>>(cand, ctxt, mcand, mctxt, W, bptr);
    gemm_max_mean_kernel<<<BB*NQ*NK, 256, SMEM_K2>>>(out);
}

// round 13
// speedup vs baseline: 1.1931x; 1.0376x over previous
#include <cuda_runtime.h>
#include <cuda_fp16.h>
#include <cstdint>

#define BB 8
#define NQ 32
#define LQ 128
#define NK 16
#define LK 256
#define DD 128
#define KQ 64
#define KK 128
#define NEGV -99999.0f
#define PADD 136 // halfs per smem row (16B pad per 256B row -> conflict-free ldmatrix)

// K2 smem: A(ctxt) 128 x PADD + B(cand) 64 x PADD halfs + rowmax[128] floats
#define SMEM_K2 ((128 + 64) * PADD * 2 + 128 * 4)

__device__ __align__(16) __half g_candSel[BB*NQ*KQ*DD];   // [token][dim]
__device__ __align__(16) __half g_ctxtSel[BB*NK*KK*DD];   // [token][dim]
__device__ int   g_candValid[BB*NQ];
__device__ float g_ctxtMask[BB*NK*KK];

__device__ __forceinline__ unsigned int fkey(float f) {
    unsigned int u = __float_as_uint(f);
    return (u & 0x80000000u) ? ~u : (u | 0x80000000u);
}
__device__ __forceinline__ int mask_mode(const unsigned char* m) {
    const unsigned int* w = (const unsigned int*)m;
    #pragma unroll
    for (int i = 0; i < 4; i++) {
        unsigned int v = w[i];
        if (v == 0x3F800000u) return 2;
        if (v > 1u) return 0;
    }
    return 1;
}
__device__ __forceinline__ bool read_mask(const unsigned char* m, int i, int mode) {
    if (mode == 0) return m[i] != 0;
    if (mode == 1) return ((const int*)m)[i] != 0;
    return ((const float*)m)[i] != 0.0f;
}

// in-warp bitonic compare-exchange (stride < 32); key one-per-thread
__device__ __forceinline__ unsigned long long warp_ce(
    unsigned long long mykey, int j, int stride, int size)
{
    unsigned long long other = __shfl_xor_sync(0xffffffffu, mykey, stride);
    bool upper   = (j & stride) != 0;
    bool descend = (j & size) == 0;
    bool takemax = descend ^ upper;
    bool gt = mykey > other;
    return (takemax == gt) ? mykey : other;
}

// ---------------------------------------------------------------------------
// Kernel 1: scores (4-way batched MLP) -> hybrid shuffle/smem bitonic top-k
// -> float4 gather. 512 threads.
// ---------------------------------------------------------------------------
__global__ __launch_bounds__(512) void select_gather_kernel(
    const float* __restrict__ cand, const float* __restrict__ ctxt,
    const unsigned char* __restrict__ mcand, const unsigned char* __restrict__ mctxt,
    const float* __restrict__ W, const float* __restrict__ bptr)
{
    __shared__ __align__(16) float Ws[DD];
    __shared__ unsigned long long keys[256];
    __shared__ int s_count;

    int tid = threadIdx.x;
    bool isCand = (blockIdx.x < BB*NQ);
    int row = isCand ? blockIdx.x : (blockIdx.x - BB*NQ);
    int L = isCand ? LQ : LK;
    int k = L >> 1;
    const float* rep = isCand ? (cand + (size_t)row * LQ * DD)
                              : (ctxt + (size_t)row * LK * DD);
    const unsigned char* mbase = isCand ? mcand : mctxt;
    int mmode = mask_mode(mbase);
    int moff  = row * L;

    if (tid < DD) Ws[tid] = W[tid];
    if (tid == 0) s_count = 0;
    __syncthreads();

    float bb = bptr[0];
    int wid = tid >> 5, lane = tid & 31;

    // scores: 16 warps, 4 tokens per warp per round (independent loads, MLP=4)
    {
        float4 w4 = ((const float4*)Ws)[lane];
        for (int t0 = wid; t0 < L; t0 += 64) {
            float acc[4];
            #pragma unroll
            for (int j = 0; j < 4; j++) {
                float4 v = ((const float4*)(rep + (t0 + j * 16) * DD))[lane];
                acc[j] = v.x*w4.x + v.y*w4.y + v.z*w4.z + v.w*w4.w;
            }
            #pragma unroll
            for (int off = 16; off; off >>= 1) {
                #pragma unroll
                for (int j = 0; j < 4; j++)
                    acc[j] += __shfl_xor_sync(0xffffffffu, acc[j], off);
            }
            if (lane == 0) {
                #pragma unroll
                for (int j = 0; j < 4; j++) {
                    int t = t0 + j * 16;
                    float s = read_mask(mbase, moff + t, mmode) ? (acc[j] + bb) : NEGV;
                    keys[t] = ((unsigned long long)fkey(s) << 32) | (unsigned int)(~t);
                }
            }
        }
    }
    __syncthreads();

    // hybrid bitonic sort, descending: stride<32 via shuffles, >=32 via smem
    {
        unsigned long long mykey = (tid < L) ? keys[tid] : 0ull;

        // sizes 2..32: fully in-warp
        if (tid < L) {
            #pragma unroll
            for (int size = 2; size <= 32; size <<= 1)
                for (int stride = size >> 1; stride > 0; stride >>= 1)
                    mykey = warp_ce(mykey, tid, stride, size);
        }

        for (int size = 64; size <= L; size <<= 1) {
            if (tid < L) keys[tid] = mykey;
            __syncthreads();
            for (int stride = size >> 1; stride >= 32; stride >>= 1) {
                if (tid < L) {
                    int j = tid ^ stride;
                    if (j > tid) {
                        bool descend = ((tid & size) == 0);
                        unsigned long long a = keys[tid], c = keys[j];
                        if (descend ? (a < c) : (a > c)) { keys[tid] = c; keys[j] = a; }
                    }
                }
                __syncthreads();
            }
            mykey = (tid < L) ? keys[tid] : 0ull;
            if (tid < L) {
                #pragma unroll
                for (int stride = 16; stride > 0; stride >>= 1)
                    mykey = warp_ce(mykey, tid, stride, size);
            }
        }
        if (tid < L) keys[tid] = mykey;
        __syncthreads();
    }

    if (isCand) {
        int cnt = 0;
        for (int j = tid; j < k; j += 512) {
            int t = (int)(~(unsigned int)keys[j]);
            if (read_mask(mbase, moff + t, mmode)) cnt++;
        }
        if (cnt) atomicAdd(&s_count, cnt);
        __syncthreads();
        if (tid == 0) g_candValid[row] = s_count;
    } else {
        for (int j = tid; j < k; j += 512) {
            int t = (int)(~(unsigned int)keys[j]);
            g_ctxtMask[row * KK + j] = read_mask(mbase, moff + t, mmode) ? 1.0f : 0.0f;
        }
    }

    // gather: 32B read -> 16B write per iteration
    __half* dst = isCand ? (g_candSel + (size_t)row * KQ * DD)
                         : (g_ctxtSel + (size_t)row * KK * DD);
    for (int e = tid; e < k * 16; e += 512) {
        int j = e >> 4, c = e & 15;
        int t = (int)(~(unsigned int)keys[j]);
        const float4* s = (const float4*)(rep + t * DD + c * 8);
        float4 v0 = s[0], v1 = s[1];
        int4 pk;
        __half2* ph = (__half2*)&pk;
        ph[0] = __floats2half2_rn(v0.x, v0.y);
        ph[1] = __floats2half2_rn(v0.z, v0.w);
        ph[2] = __floats2half2_rn(v1.x, v1.y);
        ph[3] = __floats2half2_rn(v1.z, v1.w);
        *(int4*)&dst[j * DD + c * 8] = pk;
    }
}

// ---------------------------------------------------------------------------
// Kernel 2: one block per (bq, kk). Transposed D[128 ctxt, 64 cand].
// Split-wait mainloop: first LDSM pair feeds MMAs while second pair loads.
// ---------------------------------------------------------------------------
__device__ __forceinline__ void atomicMaxF(float* addr, float v) {
    if (v >= 0.f) atomicMax((int*)addr, __float_as_int(v));
    else          atomicMin((unsigned int*)addr, __float_as_uint(v));
}
__device__ __forceinline__ void ldsm_x4(unsigned int* r, unsigned int saddr) {
    asm volatile("ldmatrix.sync.aligned.m8n8.x4.shared.b16 {%0,%1,%2,%3}, [%4];"
                 : "=r"(r[0]), "=r"(r[1]), "=r"(r[2]), "=r"(r[3]) : "r"(saddr));
}
__device__ __forceinline__ void cp16(unsigned int dst, const void* src) {
    asm volatile("cp.async.cg.shared.global [%0], [%1], 16;\n" :: "r"(dst), "l"(src));
}
__device__ __forceinline__ void mma16816(float* C, const unsigned int* A,
                                         unsigned int b0, unsigned int b1) {
    asm volatile(
        "mma.sync.aligned.m16n8k16.row.col.f32.f16.f16.f32 "
        "{%0,%1,%2,%3}, {%4,%5,%6,%7}, {%8,%9}, {%0,%1,%2,%3};\n"
        : "+f"(C[0]), "+f"(C[1]), "+f"(C[2]), "+f"(C[3])
        : "r"(A[0]), "r"(A[1]), "r"(A[2]), "r"(A[3]), "r"(b0), "r"(b1));
}

__global__ __launch_bounds__(256, 4) void gemm_max_mean_kernel(float* __restrict__ out)
{
    extern __shared__ __align__(16) unsigned char smraw[];
    __half* As  = (__half*)smraw;                       // ctxt: 128 x PADD
    __half* Bsh = (__half*)smraw + 128 * PADD;          // cand: 64 x PADD
    float*  rowmax = (float*)((__half*)smraw + (128 + 64) * PADD);  // 128
    __shared__ float sAccV, sAccM;

    int tid  = threadIdx.x;
    int lane = tid & 31, wid = tid >> 5;
    int wm = wid >> 1;
    int wn = wid & 1;
    int blk = blockIdx.x;
    int bq = blk >> 4;
    int kk = blk & 15;
    int b  = bq >> 5;
    int g  = lane >> 2;
    int cpair = (lane & 3) * 2;

    {
        const __half* Ag = g_ctxtSel + ((size_t)(b * NK + kk)) * KK * DD;
        unsigned int AsAddr = (unsigned int)__cvta_generic_to_shared(As);
        for (int i = tid; i < 128 * 16; i += 256) {
            int r = i >> 4, seg = i & 15;
            cp16(AsAddr + (r * PADD + seg * 8) * 2, &Ag[r * DD + seg * 8]);
        }
        const __half* Bg = g_candSel + (size_t)bq * KQ * DD;
        unsigned int BsAddr = (unsigned int)__cvta_generic_to_shared(Bsh);
        for (int i = tid; i < 64 * 16; i += 256) {
            int r = i >> 4, seg = i & 15;
            cp16(BsAddr + (r * PADD + seg * 8) * 2, &Bg[r * DD + seg * 8]);
        }
        asm volatile("cp.async.commit_group;\n");
    }
    if (tid < 128) rowmax[tid] = NEGV;
    if (tid == 0) { sAccV = 0.f; sAccM = 0.f; }
    int nvalid = g_candValid[bq];
    asm volatile("cp.async.wait_group 0;\n");
    __syncthreads();

    int t8   = lane >> 3;
    int rsub = lane & 7;
    unsigned int aAddr = (unsigned int)__cvta_generic_to_shared(
        &As[(wm * 32 + (t8 & 1) * 8 + rsub) * PADD + (t8 >> 1) * 8]);
    unsigned int bAddr = (unsigned int)__cvta_generic_to_shared(
        &Bsh[(wn * 32 + (t8 & 1) * 8 + rsub) * PADD + (t8 >> 1) * 8]);
    const unsigned int mtStep = 16 * PADD * 2;

    float C[2][4][4];
    #pragma unroll
    for (int mt = 0; mt < 2; mt++)
        #pragma unroll
        for (int np = 0; np < 4; np++)
            #pragma unroll
            for (int j = 0; j < 4; j++) C[mt][np][j] = 0.f;

    #pragma unroll
    for (int ks = 0; ks < 8; ks++) {
        unsigned int off = ks * 32;
        unsigned int aF0[4], aF1[4], bF0[4], bF1[4];
        // split-wait: first pair, start its MMAs, then second pair
        ldsm_x4(aF0, aAddr + off);
        ldsm_x4(bF0, bAddr + off);
        mma16816(C[0][0], aF0, bF0[0], bF0[2]);
        mma16816(C[0][1], aF0, bF0[1], bF0[3]);
        ldsm_x4(aF1, aAddr + mtStep + off);
        ldsm_x4(bF1, bAddr + mtStep + off);
        mma16816(C[1][0], aF1, bF0[0], bF0[2]);
        mma16816(C[1][1], aF1, bF0[1], bF0[3]);
        mma16816(C[0][2], aF0, bF1[0], bF1[2]);
        mma16816(C[0][3], aF0, bF1[1], bF1[3]);
        mma16816(C[1][2], aF1, bF1[0], bF1[2]);
        mma16816(C[1][3], aF1, bF1[1], bF1[3]);
    }

    #pragma unroll
    for (int mt = 0; mt < 2; mt++) {
        float m0 = NEGV, m1 = NEGV;
        #pragma unroll
        for (int np = 0; np < 4; np++) {
            int col = wn * 32 + np * 8 + cpair;
            bool v0 = (col < nvalid), v1 = (col + 1 < nvalid);
            m0 = fmaxf(m0, fmaxf(v0 ? C[mt][np][0] : NEGV, v1 ? C[mt][np][1] : NEGV));
            m1 = fmaxf(m1, fmaxf(v0 ? C[mt][np][2] : NEGV, v1 ? C[mt][np][3] : NEGV));
        }
        #pragma unroll
        for (int off = 1; off < 4; off <<= 1) {
            m0 = fmaxf(m0, __shfl_xor_sync(0xffffffffu, m0, off));
            m1 = fmaxf(m1, __shfl_xor_sync(0xffffffffu, m1, off));
        }
        if ((lane & 3) == 0) {
            int r = wm * 32 + mt * 16 + g;
            atomicMaxF(&rowmax[r],     m0);
            atomicMaxF(&rowmax[r + 8], m1);
        }
    }
    __syncthreads();

    if (tid < 128) {
        float m = g_ctxtMask[(b * NK + kk) * KK + tid];
        float v = rowmax[tid] * m;
        #pragma unroll
        for (int off = 16; off; off >>= 1) {
            v += __shfl_xor_sync(0xffffffffu, v, off);
            m += __shfl_xor_sync(0xffffffffu, m, off);
        }
        if (lane == 0) { atomicAdd(&sAccV, v); atomicAdd(&sAccM, m); }
    }
    __syncthreads();
    if (tid == 0) out[bq * NK + kk] = sAccV / sAccM;
}

// ---------------------------------------------------------------------------
extern "C" void kernel_launch(void* const* d_in, const int* in_sizes, int n_in,
                              void* d_out, int out_size)
{
    const float*         cand  = (const float*)d_in[0];
    const float*         ctxt  = (const float*)d_in[1];
    const unsigned char* mcand = (const unsigned char*)d_in[2];
    const unsigned char* mctxt = (const unsigned char*)d_in[3];
    const float*         W     = (const float*)d_in[4];
    const float*         bptr  = (const float*)d_in[5];
    float* out = (float*)d_out;

    cudaFuncSetAttribute(gemm_max_mean_kernel,
                         cudaFuncAttributeMaxDynamicSharedMemorySize, SMEM_K2);

    select_gather_kernel<<<BB*NQ + BB*NK, 512>>>(cand, ctxt, mcand, mctxt, W, bptr);
    gemm_max_mean_kernel<<<BB*NQ*NK, 256, SMEM_K2>>>(out);
}